// round 4
// baseline (speedup 1.0000x reference)
#include <cuda_runtime.h>

// Voronoi nearest-site via fine-grid candidate LUT. Reference-exact fp32:
//   a  = rn(rn(x0^2) + rn(x1^2))
//   e  = fmaf(x1, sy, rn(x0*sx))
//   d2 = rn(rn(a - 2*e) + cs),  cs = rn(rn(sx^2) + rn(sy^2))
//   argmin: ascending scan, strict <
//
// R3 -> R4: BRANCHLESS main path. Every cell entry holds exactly 4 candidate
// ids (padded by replicating the first; duplicates can't win under strict <).
// All lanes run identical code: 1 grid LDS + 4 cand LDS.128 + 1 rgb LDS.128.
// Entry 0xFFFFFFFF = fallback full scan (>4 candidates, ~never); scand has
// 256 slots with huge-distance sentinels so the speculative evals are safe.
// Grid-stride loop software-pipelines the x loads.

#define GR 96
#define NS 100
#define NCELL (GR * GR)

__device__ unsigned int g_grid[NCELL];
__device__ float4 g_cand[NS];   // sx, sy, cs, 0
__device__ float4 g_rgb[NS];    // r, g, b, 0

__global__ void build_lut(const float* __restrict__ p) {
    __shared__ float sp[2 * NS];
    if (threadIdx.x < NS) {
        sp[2 * threadIdx.x + 0] = p[1 + 5 * threadIdx.x];
        sp[2 * threadIdx.x + 1] = p[2 + 5 * threadIdx.x];
    }
    __syncthreads();

    int cell = blockIdx.x * blockDim.x + threadIdx.x;
    if (cell < NS) {
        float sx = sp[2 * cell], sy = sp[2 * cell + 1];
        float cs = __fadd_rn(__fmul_rn(sx, sx), __fmul_rn(sy, sy));
        g_cand[cell] = make_float4(sx, sy, cs, 0.0f);
        g_rgb[cell]  = make_float4(p[3 + 5 * cell], p[4 + 5 * cell], p[5 + 5 * cell], 0.0f);
    }
    if (cell >= NCELL) return;

    int gy = cell / GR;
    int gx = cell - gy * GR;
    float cx = (gx + 0.5f) * (1.0f / GR);
    float cy = (gy + 0.5f) * (1.0f / GR);

    float best = 3.4e38f;
    #pragma unroll 4
    for (int s = 0; s < NS; s++) {
        float dx = cx - sp[2 * s];
        float dy = cy - sp[2 * s + 1];
        best = fminf(best, fmaf(dx, dx, dy * dy));
    }

    // Band: d(c,s) < d(c,s*) + 2r + slack. 2r = sqrt(2)/96; slack 1e-4 covers
    // the reference formula's ~4e-7 d2 rounding noise with huge margin.
    float thr = sqrtf(best) + 0.01473139f + 1e-4f;
    float thr2 = thr * thr;

    unsigned int ids[4] = {0, 0, 0, 0};
    int cnt = 0;
    for (int s = 0; s < NS; s++) {
        float dx = cx - sp[2 * s];
        float dy = cy - sp[2 * s + 1];
        float d2 = fmaf(dx, dx, dy * dy);
        if (d2 <= thr2) {
            if (cnt < 4) ids[cnt] = (unsigned int)s;
            cnt++;
        }
    }
    unsigned int entry;
    if (cnt > 4) {
        entry = 0xFFFFFFFFu;                    // full-scan fallback
    } else {
        // Pad by replicating first candidate (ascending + strict < => padding
        // never wins; tie-break = lowest index, matching argmin).
        for (int k = cnt; k < 4; k++) ids[k] = ids[0];
        entry = ids[0] | (ids[1] << 8) | (ids[2] << 16) | (ids[3] << 24);
    }
    g_grid[cell] = entry;
}

struct SmemTables {
    unsigned int grid[NCELL];   // 36864 B
    float4 cand[256];           //  4096 B (100 real + sentinels)
    float4 rgb[NS];             //  1600 B
};

__device__ __forceinline__ float4 lookup_one(
    float px, float py,
    const unsigned int* __restrict__ sgrid,
    const float4* __restrict__ scand,
    const float4* __restrict__ srgb)
{
    int cx = (int)(px * (float)GR);
    int cy = (int)(py * (float)GR);
    unsigned int e = sgrid[cy * GR + cx];

    // reference-rounded |x|^2
    float a = __fadd_rn(__fmul_rn(px, px), __fmul_rn(py, py));

    float bd = 3.4e38f;
    int bi = 0;
    #pragma unroll
    for (int k = 0; k < 4; k++) {
        unsigned int c = (e >> (8 * k)) & 0xFFu;
        float4 s = scand[c];
        float ee = __fmaf_rn(py, s.y, __fmul_rn(px, s.x));
        float d2 = __fadd_rn(__fsub_rn(a, __fmul_rn(2.0f, ee)), s.z);
        if (d2 < bd) { bd = d2; bi = (int)c; }
    }

    if (e == 0xFFFFFFFFu) {     // ~never taken
        bd = 3.4e38f; bi = 0;
        for (int s = 0; s < NS; s++) {
            float4 sc = scand[s];
            float ee = __fmaf_rn(py, sc.y, __fmul_rn(px, sc.x));
            float d2 = __fadd_rn(__fsub_rn(a, __fmul_rn(2.0f, ee)), sc.z);
            if (d2 < bd) { bd = d2; bi = s; }
        }
    }
    return srgb[bi];
}

__global__ void __launch_bounds__(256, 5) voronoi_main(
    const float4* __restrict__ x4, float* __restrict__ out, int n)
{
    __shared__ SmemTables st;

    {
        const uint4* gg = (const uint4*)g_grid;
        uint4* sg = (uint4*)st.grid;
        #pragma unroll
        for (int i = threadIdx.x; i < NCELL / 4; i += 256) sg[i] = gg[i];
        // sentinel cands lose every comparison (huge cs)
        st.cand[threadIdx.x] = (threadIdx.x < NS)
            ? g_cand[threadIdx.x]
            : make_float4(0.0f, 0.0f, 1e30f, 0.0f);
        if (threadIdx.x < NS) st.rgb[threadIdx.x] = g_rgb[threadIdx.x];
    }
    __syncthreads();

    float4* out4 = (float4*)out;
    int tid = blockIdx.x * blockDim.x + threadIdx.x;
    int stride = gridDim.x * blockDim.x;
    int ngroups = n >> 2;

    int g = tid;
    if (g < ngroups) {
        float4 xa = x4[2 * g + 0];
        float4 xb = x4[2 * g + 1];
        while (true) {
            int ng = g + stride;
            float4 nxa, nxb;
            if (ng < ngroups) {          // prefetch next iteration
                nxa = x4[2 * ng + 0];
                nxb = x4[2 * ng + 1];
            }

            float4 c0 = lookup_one(xa.x, xa.y, st.grid, st.cand, st.rgb);
            float4 c1 = lookup_one(xa.z, xa.w, st.grid, st.cand, st.rgb);
            float4 c2 = lookup_one(xb.x, xb.y, st.grid, st.cand, st.rgb);
            float4 c3 = lookup_one(xb.z, xb.w, st.grid, st.cand, st.rgb);

            out4[3 * g + 0] = make_float4(c0.x, c0.y, c0.z, c1.x);
            out4[3 * g + 1] = make_float4(c1.y, c1.z, c2.x, c2.y);
            out4[3 * g + 2] = make_float4(c2.z, c3.x, c3.y, c3.z);

            if (ng >= ngroups) break;
            g = ng; xa = nxa; xb = nxb;
        }
    }

    // Remainder points (n % 4) — scalar path.
    int rem_start = ngroups << 2;
    for (int i = rem_start + tid; i < n; i += stride) {
        const float2* x2 = (const float2*)x4;
        float2 pt = x2[i];
        float4 c = lookup_one(pt.x, pt.y, st.grid, st.cand, st.rgb);
        out[3 * i + 0] = c.x;
        out[3 * i + 1] = c.y;
        out[3 * i + 2] = c.z;
    }
}

extern "C" void kernel_launch(void* const* d_in, const int* in_sizes, int n_in,
                              void* d_out, int out_size) {
    const float4* x = (const float4*)d_in[0];
    const float*  p = (const float*)d_in[1];
    float* out = (float*)d_out;
    int n = in_sizes[0] / 2;

    build_lut<<<(NCELL + 255) / 256, 256>>>(p);
    voronoi_main<<<740, 256>>>(x, out, n);
}

// round 5
// speedup vs baseline: 1.4247x; 1.4247x over previous
#include <cuda_runtime.h>

// Voronoi nearest-site via fine-grid candidate LUT. Reference-exact fp32:
//   a  = rn(rn(x0^2) + rn(x1^2))
//   e  = fmaf(x1, sy, rn(x0*sx))
//   d2 = rn(rn(a - 2*e) + cs),  cs = rn(rn(sx^2) + rn(sy^2))
//   argmin: ascending scan, strict <
//
// R4 -> R5: back to the branchy R2 structure (min smem traffic: single-cand
// cells do 1 LDS.32 + 1 LDS.128 only). New: GR=88 grid -> 33.4 KB smem ->
// 6 CTAs/SM (888 blocks, one wave); 2 points/thread as independent
// stride-separated chains (ILP hides LDS latency, stores stay 12B-stride
// coalesced); clamps dropped (x in [0,1) guaranteed, rounding verified safe).

#define GR 88
#define NS 100
#define NCELL (GR * GR)

__device__ unsigned int g_grid[NCELL];
__device__ float4 g_cand[NS];   // sx, sy, cs, 0
__device__ float4 g_rgb[NS];    // r, g, b, 0

__global__ void build_lut(const float* __restrict__ p) {
    __shared__ float sp[2 * NS];
    if (threadIdx.x < NS) {
        sp[2 * threadIdx.x + 0] = p[1 + 5 * threadIdx.x];
        sp[2 * threadIdx.x + 1] = p[2 + 5 * threadIdx.x];
    }
    __syncthreads();

    int cell = blockIdx.x * blockDim.x + threadIdx.x;
    if (cell < NS) {
        float sx = sp[2 * cell], sy = sp[2 * cell + 1];
        float cs = __fadd_rn(__fmul_rn(sx, sx), __fmul_rn(sy, sy));
        g_cand[cell] = make_float4(sx, sy, cs, 0.0f);
        g_rgb[cell]  = make_float4(p[3 + 5 * cell], p[4 + 5 * cell], p[5 + 5 * cell], 0.0f);
    }
    if (cell >= NCELL) return;

    int gy = cell / GR;
    int gx = cell - gy * GR;
    float cx = (gx + 0.5f) * (1.0f / GR);
    float cy = (gy + 0.5f) * (1.0f / GR);

    float best = 3.4e38f;
    #pragma unroll 4
    for (int s = 0; s < NS; s++) {
        float dx = cx - sp[2 * s];
        float dy = cy - sp[2 * s + 1];
        best = fminf(best, fmaf(dx, dx, dy * dy));
    }

    // Band: d(c,s) < d(c,s*) + 2r + slack. 2r = sqrt(2)/88 = 0.016070...;
    // slack 1e-4 covers the reference formula's ~4e-7 d2 rounding noise.
    float thr = sqrtf(best) + 0.0160697f + 1e-4f;
    float thr2 = thr * thr;

    unsigned int entry = 0;
    int cnt = 0;
    for (int s = 0; s < NS; s++) {
        float dx = cx - sp[2 * s];
        float dy = cy - sp[2 * s + 1];
        float d2 = fmaf(dx, dx, dy * dy);
        if (d2 <= thr2) {
            if (cnt < 4) entry |= ((unsigned int)s) << (8 * cnt);
            cnt++;
        }
    }
    if (cnt > 4) {
        entry = (entry & 0xFFu) | 0x0000FE00u | 0x00FF0000u | 0xFF000000u; // fallback
    } else {
        for (int k = cnt; k < 4; k++) entry |= 0xFFu << (8 * k);
    }
    g_grid[cell] = entry;
}

struct SmemTables {
    unsigned int grid[NCELL];   // 30976 B
    float4 cand[NS];            //  1600 B
    float4 rgb[NS];             //  1600 B
};

__device__ __forceinline__ float4 lookup_one(
    float px, float py,
    const unsigned int* __restrict__ sgrid,
    const float4* __restrict__ scand,
    const float4* __restrict__ srgb)
{
    int cx = (int)(px * (float)GR);   // x in [0,1) -> [0, GR-1], no clamp needed
    int cy = (int)(py * (float)GR);

    unsigned int e = sgrid[cy * GR + cx];
    int idx = (int)(e & 0xFFu);

    if ((e >> 8) != 0x00FFFFFFu) {
        float a = __fadd_rn(__fmul_rn(px, px), __fmul_rn(py, py));
        float bd = 3.4e38f;
        int bi = 0;
        if (((e >> 8) & 0xFFu) == 0xFEu) {
            for (int s = 0; s < NS; s++) {
                float4 c = scand[s];
                float ee = __fmaf_rn(py, c.y, __fmul_rn(px, c.x));
                float d2 = __fadd_rn(__fsub_rn(a, __fmul_rn(2.0f, ee)), c.z);
                if (d2 < bd) { bd = d2; bi = s; }
            }
        } else {
            #pragma unroll
            for (int k = 0; k < 4; k++) {
                unsigned int c = (e >> (8 * k)) & 0xFFu;
                if (c == 0xFFu) break;
                float4 s = scand[c];
                float ee = __fmaf_rn(py, s.y, __fmul_rn(px, s.x));
                float d2 = __fadd_rn(__fsub_rn(a, __fmul_rn(2.0f, ee)), s.z);
                if (d2 < bd) { bd = d2; bi = (int)c; }
            }
        }
        idx = bi;
    }
    return srgb[idx];
}

__global__ void __launch_bounds__(256, 6) voronoi_main(
    const float2* __restrict__ x, float* __restrict__ out, int n)
{
    __shared__ SmemTables st;

    {
        const uint4* gg = (const uint4*)g_grid;
        uint4* sg = (uint4*)st.grid;
        for (int i = threadIdx.x; i < NCELL / 4; i += 256) sg[i] = gg[i];
        if (threadIdx.x < NS) {
            st.cand[threadIdx.x] = g_cand[threadIdx.x];
            st.rgb[threadIdx.x]  = g_rgb[threadIdx.x];
        }
    }
    __syncthreads();

    int tid = blockIdx.x * blockDim.x + threadIdx.x;
    int stride = gridDim.x * blockDim.x;

    // 2 independent stride-separated points per loop iteration.
    int i = tid;
    for (; i + stride < n; i += 2 * stride) {
        int j = i + stride;
        float2 p0 = x[i];
        float2 p1 = x[j];

        float4 c0 = lookup_one(p0.x, p0.y, st.grid, st.cand, st.rgb);
        float4 c1 = lookup_one(p1.x, p1.y, st.grid, st.cand, st.rgb);

        out[3 * i + 0] = c0.x;
        out[3 * i + 1] = c0.y;
        out[3 * i + 2] = c0.z;
        out[3 * j + 0] = c1.x;
        out[3 * j + 1] = c1.y;
        out[3 * j + 2] = c1.z;
    }
    if (i < n) {
        float2 p0 = x[i];
        float4 c0 = lookup_one(p0.x, p0.y, st.grid, st.cand, st.rgb);
        out[3 * i + 0] = c0.x;
        out[3 * i + 1] = c0.y;
        out[3 * i + 2] = c0.z;
    }
}

extern "C" void kernel_launch(void* const* d_in, const int* in_sizes, int n_in,
                              void* d_out, int out_size) {
    const float2* x = (const float2*)d_in[0];
    const float*  p = (const float*)d_in[1];
    float* out = (float*)d_out;
    int n = in_sizes[0] / 2;

    build_lut<<<(NCELL + 255) / 256, 256>>>(p);
    voronoi_main<<<888, 256>>>(x, out, n);
}